// round 2
// baseline (speedup 1.0000x reference)
#include <cuda_runtime.h>
#include <cstdint>

// ---------------------------------------------------------------------------
// LSTM decoder, restructured:
//   Xproj[t,b,:] = x_t @ kernel[0:256,:]              (parallel pre-GEMM)
//   R_eff  = rec_kernel + dense_w @ kernel[256:320,:] (feedback folded in)
//   z_t    = Xproj[t] + bias_eff + h_{t-1} @ R_eff    (persistent kernel, 1 sync/step)
//   y_t    = h_t @ dense_w + dense_b
// ---------------------------------------------------------------------------

#define B_    128
#define T_    512
#define D_    256
#define U_    512
#define G4_   2048
#define OUT_  64

typedef unsigned long long ull;

// ------------------------- device scratch (static, no allocs) --------------
__device__ float g_xproj[(size_t)T_ * G4_ * B_];   // [t][col][b]  512 MB
__device__ float g_ReffP[U_ * G4_];                // permuted per-block [blk][k][c]
__device__ float g_beP[G4_];                       // bias + dense_b@Kfb, permuted
__device__ float g_brawP[G4_];                     // raw bias, permuted (t==0)
__device__ float g_hTA[U_ * B_];                   // h transposed [k][b], buf A
__device__ float g_hTB[U_ * B_];
__device__ float g_hrA[B_ * U_];                   // h row-major [b][u], buf A
__device__ float g_hrB[B_ * U_];
__device__ unsigned g_cnt = 0;
__device__ unsigned g_gen = 0;

// ------------------------- small helpers -----------------------------------
__device__ __forceinline__ void fma2(ull &acc, ull a, ull b) {
    asm("fma.rn.f32x2 %0, %1, %2, %0;" : "+l"(acc) : "l"(a), "l"(b));
}
__device__ __forceinline__ ull pack2(float x, float y) {
    ull r; asm("mov.b64 %0, {%1, %2};" : "=l"(r) : "f"(x), "f"(y)); return r;
}
__device__ __forceinline__ float2 unpack2(ull v) {
    float2 r; asm("mov.b64 {%0, %1}, %2;" : "=f"(r.x), "=f"(r.y) : "l"(v)); return r;
}
__device__ __forceinline__ float sigm(float x) {
    return __fdividef(1.f, 1.f + __expf(-x));
}
__device__ __forceinline__ float tanh_(float x) {
    float a = fabsf(x);
    float e = __expf(-2.f * a);
    float r = __fdividef(1.f - e, 1.f + e);
    return copysignf(r, x);
}

// spin grid barrier (all CTAs co-resident: 128 blocks, 1/SM by smem)
__device__ __forceinline__ void grid_sync() {
    __syncthreads();
    if (threadIdx.x == 0) {
        unsigned gen = *((volatile unsigned *)&g_gen);
        __threadfence();
        unsigned prev = atomicAdd(&g_cnt, 1u);
        if (prev == gridDim.x - 1) {
            atomicExch(&g_cnt, 0u);
            __threadfence();
            atomicAdd(&g_gen, 1u);
        } else {
            while (*((volatile unsigned *)&g_gen) == gen) { }
        }
        __threadfence();
    }
    __syncthreads();
}

// ------------------------- prep: R_eff, bias_eff ----------------------------
// R_eff[k][col] = rec[k][col] + sum_j dense_w[k][j] * kernel[256+j][col]
// stored permuted: blk = u>>2, c = (u&3)*4 + gate, at g_ReffP[blk*8192 + k*16 + c]
__global__ void prep_reff_kernel(const float *__restrict__ wk,
                                 const float *__restrict__ rec,
                                 const float *__restrict__ dw) {
    int k = blockIdx.x;
    int tid = threadIdx.x;
    __shared__ float dws[OUT_];
    if (tid < OUT_) dws[tid] = dw[k * OUT_ + tid];
    __syncthreads();
    for (int col = tid; col < G4_; col += 256) {
        float acc = rec[k * G4_ + col];
#pragma unroll 16
        for (int j = 0; j < OUT_; j++)
            acc += dws[j] * wk[(size_t)(D_ + j) * G4_ + col];
        int u = col & (U_ - 1), gate = col >> 9;
        g_ReffP[(size_t)(u >> 2) * (U_ * 16) + k * 16 + (u & 3) * 4 + gate] = acc;
    }
}

__global__ void prep_bias_kernel(const float *__restrict__ wk,
                                 const float *__restrict__ bias,
                                 const float *__restrict__ db) {
    int col = blockIdx.x * 256 + threadIdx.x;
    float acc = 0.f;
#pragma unroll 16
    for (int j = 0; j < OUT_; j++)
        acc += db[j] * wk[(size_t)(D_ + j) * G4_ + col];
    int u = col & (U_ - 1), gate = col >> 9;
    int idx = (u >> 2) * 16 + (u & 3) * 4 + gate;
    g_brawP[idx] = bias[col];
    g_beP[idx] = bias[col] + acc;
}

// ------------------------- Xproj GEMM ---------------------------------------
// g_xproj[t][col][b] = sum_d kernel[d][col] * inputs[b][t][d]
// block: (col_tile=128, t). 256 threads, 8x8 micro-tile, f32x2 FMAs.
#define XKC 16
__global__ void __launch_bounds__(256) xproj_kernel(const float *__restrict__ inp,
                                                    const float *__restrict__ wk) {
    __shared__ float sK[XKC][132];
    __shared__ float sX[XKC][136];
    int tid = threadIdx.x;
    int col0 = blockIdx.x * 128;
    int t = blockIdx.y;
    int tc = tid & 15, tb = tid >> 4;
    int c0 = tc * 8, b0 = tb * 8;

    ull acc[8][4];
#pragma unroll
    for (int c = 0; c < 8; c++)
#pragma unroll
        for (int j = 0; j < 4; j++) acc[c][j] = 0ULL;

    for (int d0 = 0; d0 < D_; d0 += XKC) {
        __syncthreads();
        {   // load kernel tile [16 d][128 col]
            int l = tid * 8;
            int dd = l >> 7, cc = l & 127;
            const float *src = wk + (size_t)(d0 + dd) * G4_ + col0 + cc;
            *(float4 *)&sK[dd][cc] = *(const float4 *)src;
            *(float4 *)&sK[dd][cc + 4] = *(const float4 *)(src + 4);
        }
        {   // load x tile transposed [16 d][128 b]
            int bb = tid >> 1, f4 = tid & 1;
            const float *src = inp + (size_t)bb * (T_ * D_) + (size_t)t * D_ + d0 + f4 * 8;
            float4 v0 = *(const float4 *)src;
            float4 v1 = *(const float4 *)(src + 4);
            int dbase = f4 * 8;
            sX[dbase + 0][bb] = v0.x; sX[dbase + 1][bb] = v0.y;
            sX[dbase + 2][bb] = v0.z; sX[dbase + 3][bb] = v0.w;
            sX[dbase + 4][bb] = v1.x; sX[dbase + 5][bb] = v1.y;
            sX[dbase + 6][bb] = v1.z; sX[dbase + 7][bb] = v1.w;
        }
        __syncthreads();
#pragma unroll
        for (int dd = 0; dd < XKC; dd++) {
            float4 a0 = *(float4 *)&sK[dd][c0];
            float4 a1 = *(float4 *)&sK[dd][c0 + 4];
            const ull *bp = (const ull *)&sX[dd][b0];
            ull bv0 = bp[0], bv1 = bp[1], bv2 = bp[2], bv3 = bp[3];
            float av[8] = {a0.x, a0.y, a0.z, a0.w, a1.x, a1.y, a1.z, a1.w};
#pragma unroll
            for (int c = 0; c < 8; c++) {
                ull ap = pack2(av[c], av[c]);
                fma2(acc[c][0], ap, bv0);
                fma2(acc[c][1], ap, bv1);
                fma2(acc[c][2], ap, bv2);
                fma2(acc[c][3], ap, bv3);
            }
        }
    }
#pragma unroll
    for (int c = 0; c < 8; c++) {
        size_t base = ((size_t)t * G4_ + col0 + c0 + c) * B_ + b0;
#pragma unroll
        for (int j = 0; j < 4; j++)
            *(ull *)&g_xproj[base + 2 * j] = acc[c][j];
    }
}

// ------------------------- persistent recurrence ----------------------------
struct SmemP {
    float Rs[U_ * 16];      // R_eff slice, [k][c], 32 KB (16B aligned first)
    float dw[U_ * OUT_];    // dense_w, 128 KB
    float red[B_ * 16];     // half-k reduction, 8 KB
    float cst[4 * B_];      // cell state [ul][b], 2 KB
    float hst[U_];          // staged h row, 2 KB
    float ypart[256];
    float be[16];
    float be0[16];
    float db[OUT_];
};

__global__ void __launch_bounds__(256, 1) lstm_persist(const float *__restrict__ dense_w,
                                                       const float *__restrict__ dense_b,
                                                       float *__restrict__ out) {
    extern __shared__ char smraw[];
    SmemP *sm = (SmemP *)smraw;
    int tid = threadIdx.x;
    int bid = blockIdx.x;
    int u0 = bid * 4;

    // one-time smem loads
    for (int i = tid * 4; i < U_ * OUT_; i += 256 * 4)
        *(float4 *)&sm->dw[i] = *(const float4 *)&dense_w[i];
    for (int i = tid * 4; i < U_ * 16; i += 256 * 4)
        *(float4 *)&sm->Rs[i] = *(const float4 *)&g_ReffP[(size_t)bid * (U_ * 16) + i];
    if (tid < OUT_) sm->db[tid] = dense_b[tid];
    if (tid < 16) {
        sm->be[tid] = g_beP[bid * 16 + tid];
        sm->be0[tid] = g_brawP[bid * 16 + tid];
    }
    for (int i = tid; i < 4 * B_; i += 256) sm->cst[i] = 0.f;
    __syncthreads();

    int b = tid & (B_ - 1);
    int half = tid >> 7;
    int p = 0;

    for (int t = 0; t < T_; t++) {
        const float *hrd = (p == 0) ? g_hTA : g_hTB;
        float *hwr = (p == 0) ? g_hTB : g_hTA;
        float *hrow = (p == 0) ? g_hrB : g_hrA;

        ull acc[8];
#pragma unroll
        for (int i = 0; i < 8; i++) acc[i] = 0ULL;

        if (t) {
            const float *hp = hrd + (half << 8) * B_ + b;
            const ulonglong2 *R2 = ((const ulonglong2 *)sm->Rs) + (size_t)(half << 8) * 4;
#pragma unroll 4
            for (int k = 0; k < 256; ++k) {
                float hv = __ldcg(hp + k * B_);     // L2-only: cross-SM producer
                ull hh = pack2(hv, hv);
                ulonglong2 r0 = R2[k * 4 + 0];
                ulonglong2 r1 = R2[k * 4 + 1];
                ulonglong2 r2 = R2[k * 4 + 2];
                ulonglong2 r3 = R2[k * 4 + 3];
                fma2(acc[0], hh, r0.x); fma2(acc[1], hh, r0.y);
                fma2(acc[2], hh, r1.x); fma2(acc[3], hh, r1.y);
                fma2(acc[4], hh, r2.x); fma2(acc[5], hh, r2.y);
                fma2(acc[6], hh, r3.x); fma2(acc[7], hh, r3.y);
            }
        }

        if (half) {
            ull *rd = ((ull *)sm->red) + b * 8;
#pragma unroll
            for (int i = 0; i < 8; i++) rd[i] = acc[i];
        }
        __syncthreads();

        if (!half) {
            const ull *rd = ((const ull *)sm->red) + b * 8;
            float z[16];
#pragma unroll
            for (int i = 0; i < 8; i++) {
                float2 v = unpack2(acc[i]);
                float2 w = unpack2(rd[i]);
                z[2 * i] = v.x + w.x;
                z[2 * i + 1] = v.y + w.y;
            }
            size_t base_t = (size_t)t * G4_ * B_;
#pragma unroll
            for (int c = 0; c < 16; c++) {
                int col = ((c & 3) << 9) + u0 + (c >> 2);
                float bb = (t == 0) ? sm->be0[c] : sm->be[c];
                z[c] += g_xproj[base_t + (size_t)col * B_ + b] + bb;
            }
            float hna[4];
#pragma unroll
            for (int ul = 0; ul < 4; ul++) {
                float zi = z[ul * 4 + 0], zf = z[ul * 4 + 1];
                float zg = z[ul * 4 + 2], zo = z[ul * 4 + 3];
                float ig = sigm(zi), fg = sigm(zf);
                float gg = tanh_(zg), og = sigm(zo);
                float cold = sm->cst[ul * B_ + b];
                float cn = fg * cold + ig * gg;
                sm->cst[ul * B_ + b] = cn;
                float hv = og * tanh_(cn);
                hna[ul] = hv;
                hwr[(u0 + ul) * B_ + b] = hv;
            }
            *(float4 *)&hrow[(size_t)b * U_ + u0] =
                make_float4(hna[0], hna[1], hna[2], hna[3]);
        }
        __threadfence();
        grid_sync();

        // ---- dense head: block bid computes y[bid, :] for this t ----
        ((float2 *)sm->hst)[tid] =
            __ldcg(((const float2 *)(hrow + (size_t)bid * U_)) + tid);
        __syncthreads();
        {
            int o = tid & (OUT_ - 1), q = tid >> 6;
            const float *hq = sm->hst + q * 128;
            const float *dwq = sm->dw + (size_t)q * 128 * OUT_ + o;
            float a0 = 0.f, a1 = 0.f, a2 = 0.f, a3 = 0.f;
#pragma unroll
            for (int u = 0; u < 128; u += 4) {
                a0 = fmaf(hq[u + 0], dwq[(u + 0) * OUT_], a0);
                a1 = fmaf(hq[u + 1], dwq[(u + 1) * OUT_], a1);
                a2 = fmaf(hq[u + 2], dwq[(u + 2) * OUT_], a2);
                a3 = fmaf(hq[u + 3], dwq[(u + 3) * OUT_], a3);
            }
            sm->ypart[tid] = a0 + a1 + a2 + a3;
        }
        __syncthreads();
        if (tid < OUT_) {
            float y = sm->ypart[tid] + sm->ypart[64 + tid] +
                      sm->ypart[128 + tid] + sm->ypart[192 + tid] + sm->db[tid];
            out[((size_t)bid * T_ + t) * OUT_ + tid] = y;
        }
        p ^= 1;
    }
}

// ------------------------- launch ------------------------------------------
extern "C" void kernel_launch(void *const *d_in, const int *in_sizes, int n_in,
                              void *d_out, int out_size) {
    const float *inputs  = (const float *)d_in[0];   // [128,512,256]
    const float *kernelw = (const float *)d_in[1];   // [320,2048]
    const float *rec     = (const float *)d_in[2];   // [512,2048]
    const float *bias    = (const float *)d_in[3];   // [2048]
    const float *dense_w = (const float *)d_in[4];   // [512,64]
    const float *dense_b = (const float *)d_in[5];   // [64]
    float *out = (float *)d_out;                     // [128,512,64]

    (void)in_sizes; (void)n_in; (void)out_size;

    cudaFuncSetAttribute(lstm_persist,
                         cudaFuncAttributeMaxDynamicSharedMemorySize,
                         (int)sizeof(SmemP));

    prep_reff_kernel<<<U_, 256>>>(kernelw, rec, dense_w);
    prep_bias_kernel<<<G4_ / 256, 256>>>(kernelw, bias, dense_b);
    xproj_kernel<<<dim3(G4_ / 128, T_), 256>>>(inputs, kernelw);
    lstm_persist<<<B_, 256, (int)sizeof(SmemP)>>>(dense_w, dense_b, out);
}

// round 3
// speedup vs baseline: 1.1973x; 1.1973x over previous
#include <cuda_runtime.h>
#include <cstdint>

// ---------------------------------------------------------------------------
// LSTM decoder, restructured:
//   Xproj[t,b,:] = x_t @ kernel[0:256,:]              (parallel pre-GEMM)
//   R_eff  = rec_kernel + dense_w @ kernel[256:320,:] (feedback folded in)
//   z_t    = Xproj[t] + bias_eff + h_{t-1} @ R_eff    (persistent kernel, 1 sync/step)
//   y_t    = h_t @ dense_w + dense_b
// R2: 512 threads, smem-staged h via cp.async.cg (double-buffered), xproj
//     prefetched at step start.
// ---------------------------------------------------------------------------

#define B_    128
#define T_    512
#define D_    256
#define U_    512
#define G4_   2048
#define OUT_  64
#define NTH   512
#define KC_   32          // k-chunk staged per cp.async round
#define NCH   (U_ / KC_)  // 16 chunks

typedef unsigned long long ull;

// ------------------------- device scratch (static, no allocs) --------------
__device__ float g_xproj[(size_t)T_ * G4_ * B_];   // [t][col][b]
__device__ float g_ReffP[U_ * G4_];                // permuted per-block [blk][k][c]
__device__ float g_beP[G4_];
__device__ float g_brawP[G4_];
__device__ float g_hTA[U_ * B_];                   // h transposed [k][b]
__device__ float g_hTB[U_ * B_];
__device__ float g_hrA[B_ * U_];                   // h row-major [b][u]
__device__ float g_hrB[B_ * U_];
__device__ unsigned g_cnt = 0;
__device__ unsigned g_gen = 0;

// ------------------------- small helpers -----------------------------------
__device__ __forceinline__ void fma2(ull &acc, ull a, ull b) {
    asm("fma.rn.f32x2 %0, %1, %2, %0;" : "+l"(acc) : "l"(a), "l"(b));
}
__device__ __forceinline__ ull pack2(float x, float y) {
    ull r; asm("mov.b64 %0, {%1, %2};" : "=l"(r) : "f"(x), "f"(y)); return r;
}
__device__ __forceinline__ float2 unpack2(ull v) {
    float2 r; asm("mov.b64 {%0, %1}, %2;" : "=f"(r.x), "=f"(r.y) : "l"(v)); return r;
}
__device__ __forceinline__ float sigm(float x) {
    return __fdividef(1.f, 1.f + __expf(-x));
}
__device__ __forceinline__ float tanh_(float x) {
    float a = fabsf(x);
    float e = __expf(-2.f * a);
    float r = __fdividef(1.f - e, 1.f + e);
    return copysignf(r, x);
}
__device__ __forceinline__ void cpasync16(uint32_t saddr, const float *g) {
    asm volatile("cp.async.cg.shared.global [%0], [%1], 16;"
                 :: "r"(saddr), "l"(g));
}
__device__ __forceinline__ void cpcommit() {
    asm volatile("cp.async.commit_group;");
}
__device__ __forceinline__ void cpwait0() {
    asm volatile("cp.async.wait_group 0;");
}

// spin grid barrier (all CTAs co-resident: 128 blocks, 1/SM by smem)
__device__ __forceinline__ void grid_sync() {
    __syncthreads();
    if (threadIdx.x == 0) {
        unsigned gen = *((volatile unsigned *)&g_gen);
        __threadfence();
        unsigned prev = atomicAdd(&g_cnt, 1u);
        if (prev == gridDim.x - 1) {
            atomicExch(&g_cnt, 0u);
            __threadfence();
            atomicAdd(&g_gen, 1u);
        } else {
            while (*((volatile unsigned *)&g_gen) == gen) { }
        }
        __threadfence();
    }
    __syncthreads();
}

// ------------------------- prep: R_eff, bias_eff ----------------------------
__global__ void prep_reff_kernel(const float *__restrict__ wk,
                                 const float *__restrict__ rec,
                                 const float *__restrict__ dw) {
    int k = blockIdx.x;
    int tid = threadIdx.x;
    __shared__ float dws[OUT_];
    if (tid < OUT_) dws[tid] = dw[k * OUT_ + tid];
    __syncthreads();
    for (int col = tid; col < G4_; col += 256) {
        float acc = rec[k * G4_ + col];
#pragma unroll 16
        for (int j = 0; j < OUT_; j++)
            acc += dws[j] * wk[(size_t)(D_ + j) * G4_ + col];
        int u = col & (U_ - 1), gate = col >> 9;
        g_ReffP[(size_t)(u >> 2) * (U_ * 16) + k * 16 + (u & 3) * 4 + gate] = acc;
    }
}

__global__ void prep_bias_kernel(const float *__restrict__ wk,
                                 const float *__restrict__ bias,
                                 const float *__restrict__ db) {
    int col = blockIdx.x * 256 + threadIdx.x;
    float acc = 0.f;
#pragma unroll 16
    for (int j = 0; j < OUT_; j++)
        acc += db[j] * wk[(size_t)(D_ + j) * G4_ + col];
    int u = col & (U_ - 1), gate = col >> 9;
    int idx = (u >> 2) * 16 + (u & 3) * 4 + gate;
    g_brawP[idx] = bias[col];
    g_beP[idx] = bias[col] + acc;
}

// ------------------------- Xproj GEMM ---------------------------------------
#define XKC 16
__global__ void __launch_bounds__(256) xproj_kernel(const float *__restrict__ inp,
                                                    const float *__restrict__ wk) {
    __shared__ float sK[XKC][132];
    __shared__ float sX[XKC][136];
    int tid = threadIdx.x;
    int col0 = blockIdx.x * 128;
    int t = blockIdx.y;
    int tc = tid & 15, tb = tid >> 4;
    int c0 = tc * 8, b0 = tb * 8;

    ull acc[8][4];
#pragma unroll
    for (int c = 0; c < 8; c++)
#pragma unroll
        for (int j = 0; j < 4; j++) acc[c][j] = 0ULL;

    for (int d0 = 0; d0 < D_; d0 += XKC) {
        __syncthreads();
        {
            int l = tid * 8;
            int dd = l >> 7, cc = l & 127;
            const float *src = wk + (size_t)(d0 + dd) * G4_ + col0 + cc;
            *(float4 *)&sK[dd][cc] = *(const float4 *)src;
            *(float4 *)&sK[dd][cc + 4] = *(const float4 *)(src + 4);
        }
        {
            int bb = tid >> 1, f4 = tid & 1;
            const float *src = inp + (size_t)bb * (T_ * D_) + (size_t)t * D_ + d0 + f4 * 8;
            float4 v0 = *(const float4 *)src;
            float4 v1 = *(const float4 *)(src + 4);
            int dbase = f4 * 8;
            sX[dbase + 0][bb] = v0.x; sX[dbase + 1][bb] = v0.y;
            sX[dbase + 2][bb] = v0.z; sX[dbase + 3][bb] = v0.w;
            sX[dbase + 4][bb] = v1.x; sX[dbase + 5][bb] = v1.y;
            sX[dbase + 6][bb] = v1.z; sX[dbase + 7][bb] = v1.w;
        }
        __syncthreads();
#pragma unroll
        for (int dd = 0; dd < XKC; dd++) {
            float4 a0 = *(float4 *)&sK[dd][c0];
            float4 a1 = *(float4 *)&sK[dd][c0 + 4];
            const ull *bp = (const ull *)&sX[dd][b0];
            ull bv0 = bp[0], bv1 = bp[1], bv2 = bp[2], bv3 = bp[3];
            float av[8] = {a0.x, a0.y, a0.z, a0.w, a1.x, a1.y, a1.z, a1.w};
#pragma unroll
            for (int c = 0; c < 8; c++) {
                ull ap = pack2(av[c], av[c]);
                fma2(acc[c][0], ap, bv0);
                fma2(acc[c][1], ap, bv1);
                fma2(acc[c][2], ap, bv2);
                fma2(acc[c][3], ap, bv3);
            }
        }
    }
#pragma unroll
    for (int c = 0; c < 8; c++) {
        size_t base = ((size_t)t * G4_ + col0 + c0 + c) * B_ + b0;
#pragma unroll
        for (int j = 0; j < 4; j++)
            *(ull *)&g_xproj[base + 2 * j] = acc[c][j];
    }
}

// ------------------------- persistent recurrence ----------------------------
struct SmemP {
    float Rs[U_ * 16];        // 32 KB   (16B aligned: first member)
    float dw[U_ * OUT_];      // 128 KB
    float hbuf[2][KC_ * B_];  // 2 x 16 KB
    float red[3 * 16 * B_];   // 24 KB  [q-1][c][b]
    float cst[4 * B_];        // 2 KB
    float hst[U_];            // 2 KB
    float ypart[NTH];         // 2 KB
    float be[16];
    float be0[16];
    float db[OUT_];
};

__global__ void __launch_bounds__(NTH, 1) lstm_persist(const float *__restrict__ dense_w,
                                                       const float *__restrict__ dense_b,
                                                       float *__restrict__ out) {
    extern __shared__ char smraw[];
    SmemP *sm = (SmemP *)smraw;
    int tid = threadIdx.x;
    int bid = blockIdx.x;
    int u0 = bid * 4;
    int b = tid & (B_ - 1);
    int q = tid >> 7;                 // k-interleave lane, 0..3

    // one-time smem loads
    for (int i = tid * 4; i < U_ * OUT_; i += NTH * 4)
        *(float4 *)&sm->dw[i] = *(const float4 *)&dense_w[i];
    for (int i = tid * 4; i < U_ * 16; i += NTH * 4)
        *(float4 *)&sm->Rs[i] = *(const float4 *)&g_ReffP[(size_t)bid * (U_ * 16) + i];
    if (tid < OUT_) sm->db[tid] = dense_b[tid];
    if (tid < 16) {
        sm->be[tid] = g_beP[bid * 16 + tid];
        sm->be0[tid] = g_brawP[bid * 16 + tid];
    }
    for (int i = tid; i < 4 * B_; i += NTH) sm->cst[i] = 0.f;
    __syncthreads();

    uint32_t hb_s[2];
    hb_s[0] = (uint32_t)__cvta_generic_to_shared(sm->hbuf[0]);
    hb_s[1] = (uint32_t)__cvta_generic_to_shared(sm->hbuf[1]);

    int p = 0;
    for (int t = 0; t < T_; t++) {
        const float *hrd = (p == 0) ? g_hTA : g_hTB;
        float *hwr = (p == 0) ? g_hTB : g_hTA;
        float *hrow = (p == 0) ? g_hrB : g_hrA;

        // prefetch xproj (DRAM) early — hidden under the GEMM
        float xpf[16];
        size_t base_t = (size_t)t * G4_ * B_;
        if (q == 0) {
#pragma unroll
            for (int c = 0; c < 16; c++) {
                int col = ((c & 3) << 9) + u0 + (c >> 2);
                xpf[c] = __ldcg(&g_xproj[base_t + (size_t)col * B_ + b]);
            }
        }

        ull acc[8];
#pragma unroll
        for (int i = 0; i < 8; i++) acc[i] = 0ULL;

        if (t) {
            // stage chunk 0
            cpasync16(hb_s[0] + tid * 16, hrd + tid * 4);
            cpasync16(hb_s[0] + (tid + NTH) * 16, hrd + (tid + NTH) * 4);
            cpcommit();

            for (int ch = 0; ch < NCH; ch++) {
                int cur = ch & 1;
                cpwait0();
                __syncthreads();
                if (ch + 1 < NCH) {
                    int nxt = cur ^ 1;
                    const float *src = hrd + (ch + 1) * (KC_ * B_);
                    cpasync16(hb_s[nxt] + tid * 16, src + tid * 4);
                    cpasync16(hb_s[nxt] + (tid + NTH) * 16, src + (tid + NTH) * 4);
                    cpcommit();
                }
                const float *hb = sm->hbuf[cur];
                int kgbase = ch * KC_ + q;
#pragma unroll
                for (int i = 0; i < 8; i++) {
                    int kl = 4 * i + q;
                    float hv = hb[kl * B_ + b];
                    ull hh = pack2(hv, hv);
                    const ulonglong2 *R2 =
                        (const ulonglong2 *)(sm->Rs + (size_t)(kgbase + 4 * i) * 16);
                    ulonglong2 r0 = R2[0], r1 = R2[1], r2 = R2[2], r3 = R2[3];
                    fma2(acc[0], hh, r0.x); fma2(acc[1], hh, r0.y);
                    fma2(acc[2], hh, r1.x); fma2(acc[3], hh, r1.y);
                    fma2(acc[4], hh, r2.x); fma2(acc[5], hh, r2.y);
                    fma2(acc[6], hh, r3.x); fma2(acc[7], hh, r3.y);
                }
            }
        }

        // reduce 4 k-partials
        if (q) {
            float *rd = sm->red + (q - 1) * (16 * B_);
#pragma unroll
            for (int i = 0; i < 8; i++) {
                float2 v = unpack2(acc[i]);
                rd[(2 * i) * B_ + b] = v.x;
                rd[(2 * i + 1) * B_ + b] = v.y;
            }
        }
        __syncthreads();

        if (q == 0) {
            float z[16];
#pragma unroll
            for (int i = 0; i < 8; i++) {
                float2 v = unpack2(acc[i]);
                z[2 * i] = v.x;
                z[2 * i + 1] = v.y;
            }
#pragma unroll
            for (int j = 0; j < 3; j++) {
                const float *rd = sm->red + j * (16 * B_);
#pragma unroll
                for (int c = 0; c < 16; c++) z[c] += rd[c * B_ + b];
            }
#pragma unroll
            for (int c = 0; c < 16; c++)
                z[c] += xpf[c] + ((t == 0) ? sm->be0[c] : sm->be[c]);

            float hna[4];
#pragma unroll
            for (int ul = 0; ul < 4; ul++) {
                float zi = z[ul * 4 + 0], zf = z[ul * 4 + 1];
                float zg = z[ul * 4 + 2], zo = z[ul * 4 + 3];
                float ig = sigm(zi), fg = sigm(zf);
                float gg = tanh_(zg), og = sigm(zo);
                float cold = sm->cst[ul * B_ + b];
                float cn = fg * cold + ig * gg;
                sm->cst[ul * B_ + b] = cn;
                float hv = og * tanh_(cn);
                hna[ul] = hv;
                hwr[(u0 + ul) * B_ + b] = hv;
            }
            *(float4 *)&hrow[(size_t)b * U_ + u0] =
                make_float4(hna[0], hna[1], hna[2], hna[3]);
        }
        __threadfence();
        grid_sync();

        // ---- dense head: block bid computes y[bid, :] for this t ----
        sm->hst[tid] = __ldcg(&hrow[(size_t)bid * U_ + tid]);
        __syncthreads();
        {
            int o = tid & (OUT_ - 1), q8 = tid >> 6;   // 8 u-groups of 64
            const float *hq = sm->hst + q8 * 64;
            const float *dwq = sm->dw + (size_t)q8 * 64 * OUT_ + o;
            float a0 = 0.f, a1 = 0.f, a2 = 0.f, a3 = 0.f;
#pragma unroll
            for (int u = 0; u < 64; u += 4) {
                a0 = fmaf(hq[u + 0], dwq[(u + 0) * OUT_], a0);
                a1 = fmaf(hq[u + 1], dwq[(u + 1) * OUT_], a1);
                a2 = fmaf(hq[u + 2], dwq[(u + 2) * OUT_], a2);
                a3 = fmaf(hq[u + 3], dwq[(u + 3) * OUT_], a3);
            }
            sm->ypart[tid] = a0 + a1 + a2 + a3;
        }
        __syncthreads();
        if (tid < OUT_) {
            float y = sm->db[tid];
#pragma unroll
            for (int j = 0; j < 8; j++) y += sm->ypart[j * 64 + tid];
            out[((size_t)bid * T_ + t) * OUT_ + tid] = y;
        }
        p ^= 1;
    }
}

// ------------------------- launch ------------------------------------------
extern "C" void kernel_launch(void *const *d_in, const int *in_sizes, int n_in,
                              void *d_out, int out_size) {
    const float *inputs  = (const float *)d_in[0];   // [128,512,256]
    const float *kernelw = (const float *)d_in[1];   // [320,2048]
    const float *rec     = (const float *)d_in[2];   // [512,2048]
    const float *bias    = (const float *)d_in[3];   // [2048]
    const float *dense_w = (const float *)d_in[4];   // [512,64]
    const float *dense_b = (const float *)d_in[5];   // [64]
    float *out = (float *)d_out;                     // [128,512,64]

    (void)in_sizes; (void)n_in; (void)out_size;

    cudaFuncSetAttribute(lstm_persist,
                         cudaFuncAttributeMaxDynamicSharedMemorySize,
                         (int)sizeof(SmemP));

    prep_reff_kernel<<<U_, 256>>>(kernelw, rec, dense_w);
    prep_bias_kernel<<<G4_ / 256, 256>>>(kernelw, bias, dense_b);
    xproj_kernel<<<dim3(G4_ / 128, T_), 256>>>(inputs, kernelw);
    lstm_persist<<<B_, 512, (int)sizeof(SmemP)>>>(dense_w, dense_b, out);
}